// round 12
// baseline (speedup 1.0000x reference)
#include <cuda_runtime.h>
#include <cuda_bf16.h>
#include <math.h>

// Problem constants
#define B_   16
#define T_   512
#define C_   8
#define S_   64
#define KSZ_ 32
#define TOUT_ 481   // T - KSZ + 1

// Scratch (no allocations allowed in kernel_launch)
// Packed kernel constants, per k (KSZ index):
//   g_kq[k*512 + sp*16 + i*2 + half] = -2 * kern_norm[s = 2*sp + half][k][i]
__device__ __align__(16) float g_kq[KSZ_ * 32 * 16];   // 16384 floats
//   g_kc[k*64 + sp*2 + half] = sum_c kern_norm[s][k][c]^2
__device__ __align__(16) float g_kc[KSZ_ * S_];        // 2048 floats

// ---------------------------------------------------------------------------
__device__ __forceinline__ void warp_red2(float& a, float& b) {
    #pragma unroll
    for (int o = 16; o > 0; o >>= 1) {
        a += __shfl_xor_sync(0xffffffffu, a, o);
        b += __shfl_xor_sync(0xffffffffu, b, o);
    }
}

// ---------------------------------------------------------------------------
// Kernel 1: kernel normalization/reorder ONLY (x-stats moved into main).
// 64 blocks (one per filter s) x 256 threads. Triggers PDL at end.
// ---------------------------------------------------------------------------
__global__ void lsd_stats_kernel(const float* __restrict__ kern) {
    __shared__ float r1[8];
    __shared__ float r2[8];
    __shared__ float s_mean, s_rstd;
    int tid = threadIdx.x;
    int wid = tid >> 5;
    int lid = tid & 31;

    int s = blockIdx.x;
    const float* kp = kern + (size_t)s * KSZ_ * C_;
    float v = kp[tid];
    float sum = v, sq = v * v;
    warp_red2(sum, sq);
    if (lid == 0) { r1[wid] = sum; r2[wid] = sq; }
    __syncthreads();
    if (tid == 0) {
        float a = 0.0f, bq = 0.0f;
        #pragma unroll
        for (int j = 0; j < 8; j++) { a += r1[j]; bq += r2[j]; }
        float mean = a * (1.0f / 256.0f);
        float var  = bq * (1.0f / 256.0f) - mean * mean;
        float std  = sqrtf(fmaxf(var, 0.0f)) + 1e-8f;
        s_mean = mean;
        s_rstd = 1.0f / std;
    }
    __syncthreads();

    float norm = (v - s_mean) * s_rstd;
    int k = tid >> 3;
    int c = tid & 7;
    int sp = s >> 1;
    int half = s & 1;
    g_kq[k * 512 + sp * 16 + c * 2 + half] = -2.0f * norm;

    float nsq = norm * norm;
    nsq += __shfl_down_sync(0xffffffffu, nsq, 4, 8);
    nsq += __shfl_down_sync(0xffffffffu, nsq, 2, 8);
    nsq += __shfl_down_sync(0xffffffffu, nsq, 1, 8);
    if (c == 0) g_kc[k * 64 + sp * 2 + half] = nsq;

    // PDL: table slice written; allow dependent grid to sync.
    cudaTriggerProgrammaticLaunchCompletion();
}

// ---------------------------------------------------------------------------
// Kernel 2: block = (1 k) x (256 t). Computes its OWN x-stats for (b, k/4)
// during the PDL-overlap phase (full 512-sample channel load + block reduce),
// then waits only for the kernel table. 4 warps split s 4-way (8 sp each);
// each lane produces 8 consecutive t from a 15-sample register window.
// Grid: (32 k, 2 t-chunks, 16 b) = 1024 blocks of 128 threads, 7/SM.
// ---------------------------------------------------------------------------
__device__ __forceinline__ unsigned long long fma2(unsigned long long a,
                                                   unsigned long long b,
                                                   unsigned long long c) {
    unsigned long long d;
    asm("fma.rn.f32x2 %0, %1, %2, %3;" : "=l"(d) : "l"(a), "l"(b), "l"(c));
    return d;
}

#define SXP_IDX(v) ((v) + ((v) >> 3))   // skewed layout: stride-8 -> stride-9

__global__ void __launch_bounds__(128, 7)
lsd_main_kernel(const float* __restrict__ x, float* __restrict__ out) {
    __shared__ float sxr[616];                        // skewed RAW channel (544 entries)
    __shared__ __align__(16) float skq[512];          // this k's packed table
    __shared__ __align__(16) float skc[64];           // this k's ||K||^2 pairs
    __shared__ float so[4][264];                      // per-warp partial mins
    __shared__ float r1[4], r2[4];                    // x-stats partials

    int tid = threadIdx.x;
    int w   = tid >> 5;          // warp -> sp quarter
    int l   = tid & 31;          // lane
    int k   = blockIdx.x;
    int t0  = blockIdx.y << 8;   // 0 or 256
    int b   = blockIdx.z;

    int cx = k >> 2;
    int m  = k & 3;

    // --- PRE-SYNC: load full raw channel (b, cx) + compute x-stats ---
    float mean, rstd;
    {
        const float* xb = x + (size_t)b * T_ * C_ + cx;
        float sum = 0.0f, sq = 0.0f;
        #pragma unroll
        for (int rep = 0; rep < 4; rep++) {
            int j = tid + rep * 128;                  // j < 512
            float v = xb[(size_t)j * C_];
            sxr[SXP_IDX(j)] = v;
            sum += v;
            sq  = fmaf(v, v, sq);
        }
        if (tid < 32) sxr[SXP_IDX(512 + tid)] = 0.0f; // pad t >= T
        warp_red2(sum, sq);
        if (l == 0) { r1[w] = sum; r2[w] = sq; }
        __syncthreads();
        float a  = r1[0] + r1[1] + r1[2] + r1[3];
        float bq = r2[0] + r2[1] + r2[2] + r2[3];
        mean = a * (1.0f / T_);
        float var = bq * (1.0f / T_) - mean * mean;
        rstd = 1.0f / (sqrtf(fmaxf(var, 0.0f)) + 1e-8f);
    }

    // Wait for kernel-table results to be visible.
    cudaGridDependencySynchronize();

    // --- POST-SYNC: stage this k's kernel table ---
    {
        const float4* src = (const float4*)(g_kq + (size_t)k * 512);
        ((float4*)skq)[tid] = src[tid];
        if (tid < 16) ((float4*)skc)[tid] = ((const float4*)(g_kc + (size_t)k * 64))[tid];
    }
    __syncthreads();

    float nmr = -mean * rstd;

    // --- per-lane register window: 15 packed {v,v}, normalized on the fly ---
    int base = t0 + l * 8 + m * 8;
    unsigned long long w2[15];
    #pragma unroll
    for (int v = 0; v < 15; v++) {
        float f = fmaf(sxr[SXP_IDX(base + v)], rstd, nmr);
        unsigned int u = __float_as_uint(f);
        w2[v] = ((unsigned long long)u << 32) | u;
    }

    // --- main loop: this warp's 8 sp (16 s values) ---
    const ulonglong2* kq2 = (const ulonglong2*)skq;     // idx: sp*4 + q
    const unsigned long long* kcp = (const unsigned long long*)skc;

    float mn[8];
    #pragma unroll
    for (int j = 0; j < 8; j++) mn[j] = 3.402823466e38f;

    #pragma unroll
    for (int spq = 0; spq < 8; spq++) {
        int sp = (w << 3) + spq;
        ulonglong2 q0 = kq2[sp * 4 + 0];
        ulonglong2 q1 = kq2[sp * 4 + 1];
        ulonglong2 q2 = kq2[sp * 4 + 2];
        ulonglong2 q3 = kq2[sp * 4 + 3];
        unsigned long long c0 = kcp[sp];
        #pragma unroll
        for (int j = 0; j < 8; j++) {
            unsigned long long d = c0;
            d = fma2(w2[j + 0], q0.x, d);
            d = fma2(w2[j + 1], q0.y, d);
            d = fma2(w2[j + 2], q1.x, d);
            d = fma2(w2[j + 3], q1.y, d);
            d = fma2(w2[j + 4], q2.x, d);
            d = fma2(w2[j + 5], q2.y, d);
            d = fma2(w2[j + 6], q3.x, d);
            d = fma2(w2[j + 7], q3.y, d);
            float lo = __uint_as_float((unsigned int)d);
            float hi = __uint_as_float((unsigned int)(d >> 32));
            mn[j] = fminf(mn[j], fminf(lo, hi));
        }
    }

    // --- ||p||^2 after the loop (w2 still live), combine into staging ---
    #pragma unroll
    for (int j = 0; j < 8; j++) {
        float acc = 0.0f;
        #pragma unroll
        for (int i = 0; i < 8; i++) {
            float f = __uint_as_float((unsigned int)w2[j + i]);
            acc = fmaf(f, f, acc);
        }
        so[w][j * 33 + l] = acc + mn[j];
    }
    __syncthreads();

    // --- combine 4 warps' s-partials, store (2 t per thread) ---
    #pragma unroll
    for (int rep = 0; rep < 2; rep++) {
        int tt = tid + rep * 128;        // local t
        int t = t0 + tt;
        if (t < TOUT_) {
            int jj = tt & 7;
            int ll = tt >> 3;
            int idx = jj * 33 + ll;
            float v = fminf(fminf(so[0][idx], so[1][idx]),
                            fminf(so[2][idx], so[3][idx]));
            out[((size_t)b * TOUT_ + t) * KSZ_ + k] = v;
        }
    }
}

extern "C" void kernel_launch(void* const* d_in, const int* in_sizes, int n_in,
                              void* d_out, int out_size) {
    const float* x    = (const float*)d_in[0];   // (16, 512, 8)
    const float* kern = (const float*)d_in[1];   // (64, 32, 8)
    float* out = (float*)d_out;                  // (16, 481, 32)

    lsd_stats_kernel<<<64, 256>>>(kern);

    // PDL: main kernel begins (channel load + x-stats) while the kernel-norm
    // kernel is still running; cudaGridDependencySynchronize orders the
    // table reads.
    cudaLaunchAttribute attrs[1];
    attrs[0].id = cudaLaunchAttributeProgrammaticStreamSerialization;
    attrs[0].val.programmaticStreamSerializationAllowed = 1;

    cudaLaunchConfig_t cfg = {};
    cfg.gridDim  = dim3(32, 2, 16);   // (k, t-chunks, batch)
    cfg.blockDim = dim3(128, 1, 1);
    cfg.dynamicSmemBytes = 0;
    cfg.stream = 0;
    cfg.attrs = attrs;
    cfg.numAttrs = 1;

    cudaLaunchKernelEx(&cfg, lsd_main_kernel, x, out);
}